// round 8
// baseline (speedup 1.0000x reference)
#include <cuda_runtime.h>
#include <cstdint>

// Problem constants
#define BB 4096
#define DD 256
#define HH 1024
#define NPROBE 10
#define STAGE_ELEMS (NPROBE * BB * DD)   // 10,485,760 per stage

// JAX threefry mode: 1 = partitionable (default since jax 0.4.30), 0 = original
#define JAX_PARTITIONABLE 1

// ---------------- device scratch (no allocations allowed) ----------------
__device__ float g_E[4ull * STAGE_ELEMS];     // 167.8 MB rademacher probes (all 4 stages)
__device__ float g_h[(size_t)BB * HH];        // tanh activations of current stage
__device__ float g_z[(size_t)BB * DD];        // z state for next stage
__device__ float g_facc[(size_t)BB * DD];     // sum_s wf_s * f_s
__device__ float g_divpart[(size_t)BB * 16];  // per-(b, k-block) divergence partials

// ---------------- threefry2x32 (exact JAX semantics) ----------------
__device__ __forceinline__ void tf2x32(uint32_t k0, uint32_t k1,
                                       uint32_t x0, uint32_t x1,
                                       uint32_t& o0, uint32_t& o1) {
  uint32_t ks2 = k0 ^ k1 ^ 0x1BD11BDAu;
  x0 += k0; x1 += k1;
#define TFR(r) { x0 += x1; x1 = (x1 << (r)) | (x1 >> (32 - (r))); x1 ^= x0; }
  TFR(13) TFR(15) TFR(26) TFR(6)   x0 += k1;  x1 += ks2 + 1u;
  TFR(17) TFR(29) TFR(16) TFR(24)  x0 += ks2; x1 += k0 + 2u;
  TFR(13) TFR(15) TFR(26) TFR(6)   x0 += k0;  x1 += k1 + 3u;
  TFR(17) TFR(29) TFR(16) TFR(24)  x0 += k1;  x1 += ks2 + 4u;
  TFR(13) TFR(15) TFR(26) TFR(6)   x0 += ks2; x1 += k0 + 5u;
#undef TFR
  o0 = x0; o1 = x1;
}

// Generate Rademacher probes for all 4 stages.
// key chain: root = threefry_seed(42) = (0,42); key_s = fold_in(root, s) = tf(root, 0, s);
// k2 = split(key_s)[1]; bits[j] per JAX random_bits; e = (bits&1)*2-1.
__global__ void gen_kernel() {
  int stage = blockIdx.y;
  __shared__ uint32_t skey[2];
  if (threadIdx.x == 0) {
    uint32_t a0, a1, c0, c1;
    tf2x32(0u, 42u, 0u, (uint32_t)stage, a0, a1);   // fold_in
#if JAX_PARTITIONABLE
    tf2x32(a0, a1, 0u, 1u, c0, c1);                 // fold-like split, key[1]
#else
    uint32_t u0, u1, v0, v1;
    tf2x32(a0, a1, 0u, 2u, u0, u1);                 // original split: counts [0,1,2,3]
    tf2x32(a0, a1, 1u, 3u, v0, v1);
    c0 = u1; c1 = v1;                               // keys[1] = second words
#endif
    skey[0] = c0; skey[1] = c1;
  }
  __syncthreads();
  uint32_t c0 = skey[0], c1 = skey[1];
  unsigned j = blockIdx.x * 256u + threadIdx.x;     // element index within stage
  uint32_t bit;
#if JAX_PARTITIONABLE
  uint32_t w0, w1;
  tf2x32(c0, c1, 0u, j, w0, w1);
  bit = (w0 ^ w1) & 1u;
#else
  const unsigned HALF = STAGE_ELEMS / 2u;
  uint32_t w0, w1;
  if (j < HALF) { tf2x32(c0, c1, j, j + HALF, w0, w1); bit = w0 & 1u; }
  else          { tf2x32(c0, c1, j - HALF, j, w0, w1); bit = w1 & 1u; }
#endif
  g_E[(size_t)stage * STAGE_ELEMS + j] = bit ? 1.0f : -1.0f;
}

// ---------------- forward GEMM 1: h = tanh(z @ W1[:256] + t*W1[256] + b1) ----------------
// M=4096, N=1024, K=256. BM=BN=64, BK=16, 256 threads, 4x4 micro-tile.
__global__ __launch_bounds__(256) void fwd1_kernel(const float* __restrict__ X,
                                                   const float* __restrict__ W1,
                                                   const float* __restrict__ b1,
                                                   float t, int useX) {
  __shared__ float sA[16][68];
  __shared__ float sB[16][64];
  const float* Z = useX ? X : g_z;
  int m0 = blockIdx.y * 64, n0 = blockIdx.x * 64;
  int tid = threadIdx.x;
  int ty = tid >> 4, tx = tid & 15;
  int arow = tid >> 2;            // 0..63
  int acol = (tid & 3) * 4;       // 0,4,8,12
  int brow = tid >> 4;            // 0..15
  int bcol = (tid & 15) * 4;      // 0..60
  float acc[4][4] = {};
  for (int kk = 0; kk < DD; kk += 16) {
    float4 av = *(const float4*)&Z[(size_t)(m0 + arow) * DD + kk + acol];
    float4 bv = *(const float4*)&W1[(size_t)(kk + brow) * HH + n0 + bcol];
    __syncthreads();
    sA[acol + 0][arow] = av.x; sA[acol + 1][arow] = av.y;
    sA[acol + 2][arow] = av.z; sA[acol + 3][arow] = av.w;
    *(float4*)&sB[brow][bcol] = bv;
    __syncthreads();
#pragma unroll
    for (int c = 0; c < 16; ++c) {
      float4 a = *(const float4*)&sA[c][ty * 4];
      float4 b = *(const float4*)&sB[c][tx * 4];
      float aa[4] = {a.x, a.y, a.z, a.w};
      float bb[4] = {b.x, b.y, b.z, b.w};
#pragma unroll
      for (int i = 0; i < 4; ++i)
#pragma unroll
        for (int j = 0; j < 4; ++j)
          acc[i][j] += aa[i] * bb[j];
    }
  }
#pragma unroll
  for (int i = 0; i < 4; ++i)
#pragma unroll
    for (int j = 0; j < 4; ++j) {
      int m = m0 + ty * 4 + i, n = n0 + tx * 4 + j;
      float u = acc[i][j] + t * W1[(size_t)DD * HH + n] + b1[n];
      g_h[(size_t)m * HH + n] = tanhf(u);
    }
}

// ---------------- forward GEMM 2 + RK4 epilogue: f = h @ W2 + b2 ----------------
// M=4096, N=256, K=1024. Also: facc (+)= wf*f; z_next = x + cz*f.
__global__ __launch_bounds__(256) void fwd2_kernel(const float* __restrict__ X,
                                                   const float* __restrict__ W2,
                                                   const float* __restrict__ b2,
                                                   float wf, float cz, int first, int writez) {
  __shared__ float sA[16][68];
  __shared__ float sB[16][64];
  int m0 = blockIdx.y * 64, n0 = blockIdx.x * 64;
  int tid = threadIdx.x;
  int ty = tid >> 4, tx = tid & 15;
  int arow = tid >> 2;
  int acol = (tid & 3) * 4;
  int brow = tid >> 4;
  int bcol = (tid & 15) * 4;
  float acc[4][4] = {};
  for (int kk = 0; kk < HH; kk += 16) {
    float4 av = *(const float4*)&g_h[(size_t)(m0 + arow) * HH + kk + acol];
    float4 bv = *(const float4*)&W2[(size_t)(kk + brow) * DD + n0 + bcol];
    __syncthreads();
    sA[acol + 0][arow] = av.x; sA[acol + 1][arow] = av.y;
    sA[acol + 2][arow] = av.z; sA[acol + 3][arow] = av.w;
    *(float4*)&sB[brow][bcol] = bv;
    __syncthreads();
#pragma unroll
    for (int c = 0; c < 16; ++c) {
      float4 a = *(const float4*)&sA[c][ty * 4];
      float4 b = *(const float4*)&sB[c][tx * 4];
      float aa[4] = {a.x, a.y, a.z, a.w};
      float bb[4] = {b.x, b.y, b.z, b.w};
#pragma unroll
      for (int i = 0; i < 4; ++i)
#pragma unroll
        for (int j = 0; j < 4; ++j)
          acc[i][j] += aa[i] * bb[j];
    }
  }
#pragma unroll
  for (int i = 0; i < 4; ++i)
#pragma unroll
    for (int j = 0; j < 4; ++j) {
      int m = m0 + ty * 4 + i, n = n0 + tx * 4 + j;
      float f = acc[i][j] + b2[n];
      size_t idx = (size_t)m * DD + n;
      float fa = wf * f;
      if (first) g_facc[idx] = fa; else g_facc[idx] += fa;
      if (writez) g_z[idx] = X[idx] + cz * f;
    }
}

// ---------------- probe kernel: S[b,k] = sum_i v_i*w_i; div partial = sum_k (1-h^2)*S ----
// Tile 64(b) x 64(k), full c-slab (256) of W1/W2 columns in smem, per-probe E slab.
// 256 threads, 4x4 dual micro-tile. Dynamic smem: 3 * 256*68*4 = 208,896 B.
__global__ __launch_bounds__(256) void probe_kernel(const float* __restrict__ W1,
                                                    const float* __restrict__ W2,
                                                    int stage, float wstage, int first) {
  extern __shared__ float sm[];
  float* sW1 = sm;                 // [256][68] : sW1[c*68 + kk] = W1[c, k0+kk]
  float* sW2 = sm + 256 * 68;      // [256][68] : sW2[c*68 + kk] = W2[k0+kk, c]
  float* sE  = sm + 2 * 256 * 68;  // [256][68] : sE[c*68 + bb]  = E[i, b0+bb, c]
  int k0 = blockIdx.x * 64;
  int b0 = blockIdx.y * 64;
  int tid = threadIdx.x;
  int ty = tid >> 4, tx = tid & 15;

  { // load W1 column slab (64 cols, all 256 rows)
    int kk = (tid & 15) * 4;
#pragma unroll
    for (int r = 0; r < 16; ++r) {
      int c = r * 16 + (tid >> 4);
      float4 v = *(const float4*)&W1[(size_t)c * HH + k0 + kk];
      *(float4*)&sW1[c * 68 + kk] = v;
    }
  }
  // load W2 row slab transposed
  for (int r = 0; r < 64; ++r)
    sW2[tid * 68 + r] = W2[(size_t)(k0 + r) * DD + tid];

  float S[4][4] = {};
  const float* Ebase = g_E + (size_t)stage * STAGE_ELEMS + (size_t)b0 * DD;
  for (int i = 0; i < NPROBE; ++i) {
    __syncthreads();
    const float* Ep = Ebase + (size_t)i * BB * DD;
    for (int r = 0; r < 64; ++r)
      sE[tid * 68 + r] = Ep[(size_t)r * DD + tid];
    __syncthreads();
    float v[4][4] = {}, w[4][4] = {};
#pragma unroll 8
    for (int c = 0; c < DD; ++c) {
      float4 a = *(const float4*)&sE[c * 68 + ty * 4];
      float4 p = *(const float4*)&sW1[c * 68 + tx * 4];
      float4 q = *(const float4*)&sW2[c * 68 + tx * 4];
      float aa[4] = {a.x, a.y, a.z, a.w};
      float pp[4] = {p.x, p.y, p.z, p.w};
      float qq[4] = {q.x, q.y, q.z, q.w};
#pragma unroll
      for (int bi = 0; bi < 4; ++bi)
#pragma unroll
        for (int kj = 0; kj < 4; ++kj) {
          v[bi][kj] += aa[bi] * pp[kj];
          w[bi][kj] += aa[bi] * qq[kj];
        }
    }
#pragma unroll
    for (int bi = 0; bi < 4; ++bi)
#pragma unroll
      for (int kj = 0; kj < 4; ++kj)
        S[bi][kj] += v[bi][kj] * w[bi][kj];
  }

  // epilogue: weight by (1 - h^2), reduce over this block's 64 k's
  float part[4];
#pragma unroll
  for (int bi = 0; bi < 4; ++bi) {
    int b = b0 + ty * 4 + bi;
    float acc = 0.f;
#pragma unroll
    for (int kj = 0; kj < 4; ++kj) {
      float hh = g_h[(size_t)b * HH + k0 + tx * 4 + kj];
      acc += S[bi][kj] * (1.f - hh * hh);
    }
    part[bi] = acc;
  }
#pragma unroll
  for (int off = 8; off > 0; off >>= 1)
#pragma unroll
    for (int bi = 0; bi < 4; ++bi)
      part[bi] += __shfl_down_sync(0xFFFFFFFFu, part[bi], off);
  if (tx == 0) {
#pragma unroll
    for (int bi = 0; bi < 4; ++bi) {
      int b = b0 + ty * 4 + bi;
      size_t idx = (size_t)b * 16 + blockIdx.x;
      float val = wstage * part[bi];
      if (first) g_divpart[idx] = val; else g_divpart[idx] += val;
    }
  }
}

// ---------------- final: assemble output (2, 4096, 257) ----------------
__global__ void final_kernel(const float* __restrict__ X, float* __restrict__ out) {
  int idx = blockIdx.x * blockDim.x + threadIdx.x;
  if (idx >= BB * 257) return;
  int b = idx / 257, c = idx % 257;
  float y0, y1;
  if (c < DD) {
    float xv = X[(size_t)b * DD + c];
    y0 = xv;
    y1 = xv + g_facc[(size_t)b * DD + c] * (1.0f / 6.0f);
  } else {
    y0 = 0.0f;
    float dacc = 0.f;
#pragma unroll
    for (int kb = 0; kb < 16; ++kb) dacc += g_divpart[(size_t)b * 16 + kb];
    y1 = -dacc * (1.0f / 60.0f);   // -(1/6) * mean over 10 probes of weighted stage sums
  }
  out[idx] = y0;
  out[(size_t)BB * 257 + idx] = y1;
}

// ---------------- launch ----------------
extern "C" void kernel_launch(void* const* d_in, const int* in_sizes, int n_in,
                              void* d_out, int out_size) {
  const float* x  = (const float*)d_in[0];
  const float* W1 = (const float*)d_in[1];
  const float* b1 = (const float*)d_in[2];
  const float* W2 = (const float*)d_in[3];
  const float* b2 = (const float*)d_in[4];
  float* out = (float*)d_out;

  const int PROBE_SMEM = 3 * 256 * 68 * (int)sizeof(float);  // 208,896 B
  cudaFuncSetAttribute(probe_kernel, cudaFuncAttributeMaxDynamicSharedMemorySize, PROBE_SMEM);

  // generate all probes (4 stages x 10 probes x 4096 x 256)
  gen_kernel<<<dim3(STAGE_ELEMS / 256, 4), 256>>>();

  const float ts[4] = {0.0f, 0.5f, 0.5f, 1.0f};   // RK4 stage times
  const float cz[4] = {0.5f, 0.5f, 1.0f, 0.0f};   // next-state coefficient
  const float wf[4] = {1.0f, 2.0f, 2.0f, 1.0f};   // RK4 combine weights

  for (int s = 0; s < 4; ++s) {
    fwd1_kernel<<<dim3(HH / 64, BB / 64), 256>>>(x, W1, b1, ts[s], s == 0 ? 1 : 0);
    probe_kernel<<<dim3(HH / 64, BB / 64), 256, PROBE_SMEM>>>(W1, W2, s, wf[s], s == 0 ? 1 : 0);
    fwd2_kernel<<<dim3(DD / 64, BB / 64), 256>>>(x, W2, b2, wf[s], cz[s],
                                                 s == 0 ? 1 : 0, s < 3 ? 1 : 0);
  }

  final_kernel<<<(BB * 257 + 255) / 256, 256>>>(x, out);
}